// round 17
// baseline (speedup 1.0000x reference)
#include <cuda_runtime.h>
#include <cuda_bf16.h>
#include <cstdint>

// Decoder (Conv-TasNet): out = overlap_add( (mixture_w * est_mask)^T @ W^T, step=L/2 )
// mixture_w/est_mask [B, N, K] f32, W [L, N] f32, out [B, T] f32
// B=4, N=512, K=16000, L=16, step=8, T = 8*(K-1)+16 = 128008
//
// R17 = R16 (per-thread cp.async ring, measured 2.5 GB/s/warp -- 2x any
// register variant) scaled to 2x residency: NSPLIT=8 -> 800 blocks =
// 5.4 blocks/SM; smem 44KB and __launch_bounds__(160,5) both cap at 5
// blocks/SM -> ~25 warps/SM, each holding 7KB continuously in flight.

#define DEC_B 4
#define DEC_N 512
#define DEC_K 16000
#define DEC_L 16
#define DEC_STEP 8
#define DEC_T (DEC_STEP * (DEC_K - 1) + DEC_L)   // 128008

#define TPB 160                       // 5 warps; block covers 640 k
#define NSPLIT 8
#define NCHUNK (DEC_N / NSPLIT)       // 64 n-rows per block
#define KPT 4                         // frames per thread
#define KPW 128                       // k per warp (32 lanes x 4)
#define DEPTH 8                       // cp.async ring stages
#define NACC 20                       // f32x2 accumulators (40 out positions)

// smem: Ws = 1024 floats (4KB); ring = 5 warps x 8 stages x 1KB (m 512B + e 512B)
#define SMEM_WS_FLOATS (NCHUNK * DEC_L)                          // 1024
#define SMEM_WS_BYTES  (SMEM_WS_FLOATS * 4)                      // 4096
#define SMEM_TOTAL_FLOATS (SMEM_WS_FLOATS + 5 * DEPTH * 256)     // 11264 = 44KB

typedef unsigned long long u64t;

#define FMA_F32X2(d, a, b, c) \
    asm("fma.rn.f32x2 %0, %1, %2, %3;" : "=l"(d) : "l"(a), "l"(b), "l"(c))

#define CP16(dst_u32, src_ptr) \
    asm volatile("cp.async.cg.shared.global [%0], [%1], 16;" \
                 :: "r"(dst_u32), "l"(src_ptr) : "memory")
#define CP_COMMIT() asm volatile("cp.async.commit_group;" ::: "memory")
#define CP_WAIT(n)  asm volatile("cp.async.wait_group %0;" :: "n"(n) : "memory")

__global__ __launch_bounds__(TPB, 5)
void decoder_kernel(const float* __restrict__ mw,
                    const float* __restrict__ em,
                    const float* __restrict__ W,
                    float* __restrict__ out)
{
    __shared__ __align__(16) float smem[SMEM_TOTAL_FLOATS];
    float* Ws = smem;   // [64][16] transposed W chunk

    const int nb = blockIdx.z * NCHUNK;
    for (int i = threadIdx.x; i < NCHUNK * DEC_L; i += TPB) {
        int n = i >> 4;
        int l = i & 15;
        Ws[i] = W[l * DEC_N + nb + n];
    }
    __syncthreads();    // only sync in the kernel (W visibility)

    const int w    = threadIdx.x >> 5;
    const int lane = threadIdx.x & 31;
    const int b    = blockIdx.y;
    const int k0   = blockIdx.x * (TPB * KPT) + w * KPW + lane * KPT;  // < 16000 always

    // Per-thread global cursors: this lane's 16B slot in row n.
    const size_t base = (size_t)b * DEC_N * DEC_K + (size_t)nb * DEC_K + k0;
    const float* im = mw + base;
    const float* ie = em + base;

    // Per-thread smem slot addresses.
    uint32_t sb;
    {
        void* p = smem;
        asm("{ .reg .u64 t; cvta.to.shared.u64 t, %1; cvt.u32.u64 %0, t; }"
            : "=r"(sb) : "l"(p));
    }
    // ring base for this thread: after Ws, warp region 8KB, lane slot 16B
    const uint32_t rbase = sb + SMEM_WS_BYTES
                         + (uint32_t)w * (DEPTH * 1024u) + (uint32_t)lane * 16u;

    // Prologue: stages 0..DEPTH-2 in flight (7KB/warp).
#pragma unroll
    for (int s = 0; s < DEPTH - 1; ++s) {
        uint32_t d = rbase + (uint32_t)s * 1024u;
        CP16(d, im);
        CP16(d + 512u, ie);
        im += DEC_K;
        ie += DEC_K;
        CP_COMMIT();
    }

    // 40 fp32 out positions as 20 f32x2 pairs. Frame f (0..3) covers
    // positions 8f..8f+15 = pairs 4f..4f+7.
    u64t accp[NACC];
#pragma unroll
    for (int i = 0; i < NACC; ++i) accp[i] = 0ull;

#pragma unroll 1
    for (int n = 0; n < NCHUNK; ++n) {
        // issue stage n+DEPTH-1 (own 16B only), commit ALWAYS (group accounting)
        if (n + DEPTH - 1 < NCHUNK) {
            uint32_t d = rbase + (uint32_t)((n + DEPTH - 1) & (DEPTH - 1)) * 1024u;
            CP16(d, im);
            CP16(d + 512u, ie);
            im += DEC_K;
            ie += DEC_K;
        }
        CP_COMMIT();
        CP_WAIT(DEPTH - 1);   // oldest group (stage n) complete for THIS thread

        uint32_t r = rbase + (uint32_t)(n & (DEPTH - 1)) * 1024u;
        float4 m, e;
        asm volatile("ld.shared.v4.f32 {%0,%1,%2,%3}, [%4];"
                     : "=f"(m.x), "=f"(m.y), "=f"(m.z), "=f"(m.w) : "r"(r));
        asm volatile("ld.shared.v4.f32 {%0,%1,%2,%3}, [%4];"
                     : "=f"(e.x), "=f"(e.y), "=f"(e.z), "=f"(e.w) : "r"(r + 512u));

        // compute: 4 FMUL + 4 packs + 4 LDS.128 (W, broadcast) + 32 FFMA2
        float p0 = m.x * e.x;
        float p1 = m.y * e.y;
        float p2 = m.z * e.z;
        float p3 = m.w * e.w;
        u64t pp[KPT];
        asm("mov.b64 %0, {%1, %1};" : "=l"(pp[0]) : "f"(p0));
        asm("mov.b64 %0, {%1, %1};" : "=l"(pp[1]) : "f"(p1));
        asm("mov.b64 %0, {%1, %1};" : "=l"(pp[2]) : "f"(p2));
        asm("mov.b64 %0, {%1, %1};" : "=l"(pp[3]) : "f"(p3));

        const ulonglong2* wq = reinterpret_cast<const ulonglong2*>(&Ws[n * DEC_L]);
#pragma unroll
        for (int q = 0; q < 4; ++q) {
            ulonglong2 w2 = wq[q];      // pairs j = 2q, 2q+1
#pragma unroll
            for (int f = 0; f < KPT; ++f) {
                FMA_F32X2(accp[4 * f + 2 * q],     w2.x, pp[f], accp[4 * f + 2 * q]);
                FMA_F32X2(accp[4 * f + 2 * q + 1], w2.y, pp[f], accp[4 * f + 2 * q + 1]);
            }
        }
    }

    // Scatter-add 40 unique positions (frames k0..k0+3). Interior overlaps
    // merged in registers; <= 2*NSPLIT = 16 atomic fp32 contributions per
    // output element (order-insensitive).
    float* __restrict__ op = out + (size_t)b * DEC_T + (size_t)k0 * DEC_STEP;
#pragma unroll
    for (int i = 0; i < NACC; ++i) {
        float lo, hi;
        asm("mov.b64 {%0, %1}, %2;" : "=f"(lo), "=f"(hi) : "l"(accp[i]));
        atomicAdd(&op[2 * i],     lo);
        atomicAdd(&op[2 * i + 1], hi);
    }
}

extern "C" void kernel_launch(void* const* d_in, const int* in_sizes, int n_in,
                              void* d_out, int out_size)
{
    const float* mixture_w = (const float*)d_in[0];  // [B, N, K]
    const float* est_mask  = (const float*)d_in[1];  // [B, N, K]
    const float* W         = (const float*)d_in[2];  // [L, N]
    float* out = (float*)d_out;                       // [B, T]

    cudaMemsetAsync(out, 0, (size_t)out_size * sizeof(float), 0);

    dim3 grid(DEC_K / (TPB * KPT), DEC_B, NSPLIT);   // (25, 4, 8) = 800 blocks
    decoder_kernel<<<grid, TPB>>>(mixture_w, est_mask, W, out);
}